// round 17
// baseline (speedup 1.0000x reference)
#include <cuda_runtime.h>
#include <cstdint>

#define D_F      1032        // floats per weight row
#define CHUNK_F4 64          // float4 columns per chunk (4 chunks cover 256, +2 tail)
#define NCHUNK   4
#define MAX_ACTIVE 32
#define BATCH    4096
#define THREADS  64          // 2 warps; warp w owns row 2*blockIdx.x + w
#define MINBLOCKS 32         // hard-pin 32 regs -> 32 CTAs/SM, full occupancy

__global__ __launch_bounds__(THREADS, MINBLOCKS)
void ft_v8_kernel(const int*   __restrict__ idx0,
                  const float* __restrict__ val0,
                  const int*   __restrict__ idx1,
                  const float* __restrict__ val1,
                  const float* __restrict__ W,
                  const float* __restrict__ bias,
                  float*       __restrict__ out)
{
    const int bp    = blockIdx.x;        // row pair 0..4095 (rows 2bp, 2bp+1)
    const int chunk = blockIdx.y;        // 0..3 : slow dim -> L2 phases
    const int tid   = threadIdx.x;
    const int w     = tid >> 5;          // warp id -> which row of the pair
    const int lane  = tid & 31;

    __shared__ int   sOff[2][MAX_ACTIVE];   // row offsets in FLOAT units
    __shared__ float sVal[2][MAX_ACTIVE];

    const int r = 2 * bp + w;            // global row 0..8191 (never mixes sets)
    {
        const int*   idx; const float* val; int row;
        if (r < BATCH) { idx = idx0; val = val0; row = r; }
        else           { idx = idx1; val = val1; row = r - BATCH; }
        sOff[w][lane] = idx[row * MAX_ACTIVE + lane] * D_F;   // fits int (46.5M)
        sVal[w][lane] = val[row * MAX_ACTIVE + lane];
    }
    __syncthreads();

    // This lane's 8 float columns: [chunk*256 + lane*8, +8). Byte offset
    // chunk*1024 + lane*32 and row stride 4128 B are both 32B-multiples ->
    // every v8 load below is 32B-aligned.
    const int cf = chunk * 256 + lane * 8;
    const float* __restrict__ Wc = W + cf;

    float4 a0 = *(const float4*)(bias + cf);
    float4 a1 = *(const float4*)(bias + cf + 4);

    #pragma unroll 4
    for (int k = 0; k < MAX_ACTIVE; ++k) {
        const float* p = Wc + sOff[w][k];
        float r0, r1, r2, r3, r4, r5, r6, r7;
        asm("ld.global.nc.v8.f32 {%0,%1,%2,%3,%4,%5,%6,%7}, [%8];"
            : "=f"(r0), "=f"(r1), "=f"(r2), "=f"(r3),
              "=f"(r4), "=f"(r5), "=f"(r6), "=f"(r7)
            : "l"(p));
        const float v = sVal[w][k];
        a0.x = fmaf(r0, v, a0.x);
        a0.y = fmaf(r1, v, a0.y);
        a0.z = fmaf(r2, v, a0.z);
        a0.w = fmaf(r3, v, a0.w);
        a1.x = fmaf(r4, v, a1.x);
        a1.y = fmaf(r5, v, a1.y);
        a1.z = fmaf(r6, v, a1.z);
        a1.w = fmaf(r7, v, a1.w);
    }

    // Streaming stores: written once, never re-read.
    float* o = out + (size_t)r * D_F + cf;
    __stcs((float4*)o,     a0);
    __stcs((float4*)o + 1, a1);

    // Tail floats 1024..1031 (chunk 3 only): lane l contributes feature k=l,
    // one aligned v8 load (byte offset 4096 within the row), 8 shfl reductions.
    if (chunk == 3) {
        const float* pt = W + sOff[w][lane] + 1024;
        float t0, t1, t2, t3, t4, t5, t6, t7;
        asm("ld.global.nc.v8.f32 {%0,%1,%2,%3,%4,%5,%6,%7}, [%8];"
            : "=f"(t0), "=f"(t1), "=f"(t2), "=f"(t3),
              "=f"(t4), "=f"(t5), "=f"(t6), "=f"(t7)
            : "l"(pt));
        const float v = sVal[w][lane];
        t0 *= v; t1 *= v; t2 *= v; t3 *= v;
        t4 *= v; t5 *= v; t6 *= v; t7 *= v;
        #pragma unroll
        for (int s = 16; s >= 1; s >>= 1) {
            t0 += __shfl_xor_sync(0xffffffffu, t0, s);
            t1 += __shfl_xor_sync(0xffffffffu, t1, s);
            t2 += __shfl_xor_sync(0xffffffffu, t2, s);
            t3 += __shfl_xor_sync(0xffffffffu, t3, s);
            t4 += __shfl_xor_sync(0xffffffffu, t4, s);
            t5 += __shfl_xor_sync(0xffffffffu, t5, s);
            t6 += __shfl_xor_sync(0xffffffffu, t6, s);
            t7 += __shfl_xor_sync(0xffffffffu, t7, s);
        }
        if (lane == 0) {
            float* ot = out + (size_t)r * D_F + 1024;
            const float* bt = bias + 1024;
            __stcs((float4*)ot,
                   make_float4(bt[0] + t0, bt[1] + t1, bt[2] + t2, bt[3] + t3));
            __stcs((float4*)ot + 1,
                   make_float4(bt[4] + t4, bt[5] + t5, bt[6] + t6, bt[7] + t7));
        }
    }
}

extern "C" void kernel_launch(void* const* d_in, const int* in_sizes, int n_in,
                              void* d_out, int out_size)
{
    // metadata order:
    //   0: feature_indices_0  int32  [4096, 32]
    //   1: feature_values_0   f32    [4096, 32]
    //   2: feature_indices_1  int32  [4096, 32]
    //   3: feature_values_1   f32    [4096, 32]
    //   4: merged_weight      f32    [45056, 1032]
    //   5: bias               f32    [1032]
    const int*   idx0 = (const int*)  d_in[0];
    const float* val0 = (const float*)d_in[1];
    const int*   idx1 = (const int*)  d_in[2];
    const float* val1 = (const float*)d_in[3];
    const float* W    = (const float*)d_in[4];
    const float* bias = (const float*)d_in[5];

    float* out = (float*)d_out;      // [8192, 1032] : out0 then out1

    dim3 grid(BATCH, NCHUNK);        // 4096 row pairs x 4 column phases
    ft_v8_kernel<<<grid, THREADS>>>(idx0, val0, idx1, val1, W, bias, out);
}